// round 9
// baseline (speedup 1.0000x reference)
#include <cuda_runtime.h>
#include <cuda_bf16.h>
#include <cstdint>
#include <math.h>

// Problem constants
#define B_  4
#define L_  1024
#define D_  768
#define H_  12
#define NE_ 42
#define M_  8
#define P_  (NE_*(NE_-1))      // 1722 ordered pairs
#define NPU 861                // unordered pairs (i<j)
#define MP  896                // NPU padded to 128
#define EPS_H 1.2e-4f
#define EH  (NE_*H_)           // 504

// Input element counts
#define SZ_SO   (B_*L_*D_)
#define SZ_ATT  (B_*H_*L_*L_)
#define SZ_HTS  (B_*P_*2)
#define SZ_MSK  (B_*NE_*M_)

// Scratch (zero-init; pad rows >= NPU stay zero)
__device__ float          g_ea[B_*L_*EH];         // E [b, l, e, h]
__device__ __nv_bfloat16  g_Xhi[B_*MP*L_];
__device__ __nv_bfloat16  g_Xlo[B_*MP*L_];
__device__ __nv_bfloat16  g_Bhi[B_*D_*L_];
__device__ __nv_bfloat16  g_Blo[B_*D_*L_];
__device__ float          g_xpart[B_*32*NPU];     // per-l-chunk partial sums
__device__ float          g_scale[B_*NPU];
__device__ int            g_p2p[B_*NE_*NE_];
__device__ int            g_pos[B_*NE_*M_];
__device__ int            g_ht [B_*P_*2];

// ===========================================================================
// PTX helpers (baseline ISA only — sm_103 non-'a' target: no tcgen05)
// ===========================================================================
__device__ __forceinline__ uint32_t smem_u32(const void* p) {
    uint32_t a;
    asm("{ .reg .u64 t; cvta.to.shared.u64 t, %1; cvt.u32.u64 %0, t; }"
        : "=r"(a) : "l"(p));
    return a;
}
__device__ __forceinline__ void ldm_x4(uint32_t* r, uint32_t addr) {
    asm volatile("ldmatrix.sync.aligned.m8n8.x4.shared.b16 {%0,%1,%2,%3}, [%4];"
        : "=r"(r[0]), "=r"(r[1]), "=r"(r[2]), "=r"(r[3]) : "r"(addr));
}
__device__ __forceinline__ void mma_bf16(float* d, const uint32_t* a,
                                         const uint32_t* b) {
    asm volatile("mma.sync.aligned.m16n8k16.row.col.f32.bf16.bf16.f32 "
        "{%0,%1,%2,%3}, {%4,%5,%6,%7}, {%8,%9}, {%0,%1,%2,%3};"
        : "+f"(d[0]), "+f"(d[1]), "+f"(d[2]), "+f"(d[3])
        : "r"(a[0]), "r"(a[1]), "r"(a[2]), "r"(a[3]), "r"(b[0]), "r"(b[1]));
}
__device__ __forceinline__ void cpa16(uint32_t s, const void* g) {
    asm volatile("cp.async.cg.shared.global [%0], [%1], 16;" :: "r"(s), "l"(g));
}
#define CP_COMMIT() asm volatile("cp.async.commit_group;" ::: "memory")
#define CP_WAIT(n)  asm volatile("cp.async.wait_group %0;" :: "n"(n) : "memory")

// ===========================================================================
// K0: int width detect + convert + p2p map (one block)
// ===========================================================================
__global__ void k_prep(const int* __restrict__ posw, const int* __restrict__ htsw) {
    __shared__ int s_pos64, s_hts64;
    if (threadIdx.x == 0) {
        int nz = 0;
        for (int w = 1; w < 33; w += 2) nz |= posw[w];
        s_pos64 = (nz == 0) ? 1 : 0;
        nz = 0;
        for (int w = 1; w < 33; w += 2) nz |= htsw[w];
        s_hts64 = (nz == 0) ? 1 : 0;
    }
    __syncthreads();
    int sp = s_pos64 ? 2 : 1;
    for (int t = threadIdx.x; t < B_*NE_*M_; t += blockDim.x)
        g_pos[t] = posw[(size_t)t * sp] + 1;          // fold +OFFSET
    int sh = s_hts64 ? 2 : 1;
    for (int t = threadIdx.x; t < B_*P_*2; t += blockDim.x)
        g_ht[t] = htsw[(size_t)t * sh];
    __syncthreads();
    for (int t = threadIdx.x; t < B_*P_; t += blockDim.x) {
        int b = t / P_;
        int i = g_ht[(size_t)t * 2 + 0];
        int j = g_ht[(size_t)t * 2 + 1];
        g_p2p[(b * NE_ + i) * NE_ + j] = t - b * P_;
    }
}

// ===========================================================================
// K1: entity_embed  (grid = B*NE, block = D)
// ===========================================================================
__global__ void k_entity_embed(const float* __restrict__ so,
                               const float* __restrict__ mask,
                               float* __restrict__ out_ee) {
    int be = blockIdx.x;
    int b = be / NE_;
    int d = threadIdx.x;

    __shared__ int   s_row[M_];
    __shared__ float s_mk[M_];
    if (threadIdx.x < M_) {
        s_mk[threadIdx.x]  = mask[(size_t)be * M_ + threadIdx.x];
        s_row[threadIdx.x] = g_pos[be * M_ + threadIdx.x];
    }
    __syncthreads();

    float v[M_];
    float mx = -INFINITY;
#pragma unroll
    for (int m = 0; m < M_; m++) {
        if (s_mk[m] > 0.f) {
            v[m] = so[((size_t)b * L_ + s_row[m]) * D_ + d];
            mx = fmaxf(mx, v[m]);
        } else v[m] = -INFINITY;
    }
    float s = 0.f;
#pragma unroll
    for (int m = 0; m < M_; m++) s += __expf(v[m] - mx);
    out_ee[(size_t)be * D_ + d] = logf(s) + mx;
}

// ===========================================================================
// K2: entity_att -> E[b, l, e, h].  grid = (32 l-chunks, B), block = 256.
// SMEM tile Et[c][l] (c = e*12+h), stride 33 (conflict-free both phases).
// ===========================================================================
__global__ __launch_bounds__(256)
void k_entity_att(const float* __restrict__ att,
                  const float* __restrict__ mask) {
    extern __shared__ float Et[];              // EH x 33 floats
    __shared__ float s_mk[NE_*M_];
    __shared__ int   s_row[NE_*M_];
    __shared__ float s_inv[NE_];

    int lc = blockIdx.x, b = blockIdx.y;
    int lane = threadIdx.x & 31;
    int grp  = threadIdx.x >> 5;               // 8 groups
    int l    = lc * 32 + lane;

    for (int t = threadIdx.x; t < NE_*M_; t += 256) {
        s_mk[t]  = mask[(size_t)b * NE_ * M_ + t];
        s_row[t] = g_pos[b * NE_ * M_ + t];
    }
    __syncthreads();
    if (threadIdx.x < NE_) {
        float c = 0.f;
#pragma unroll
        for (int m = 0; m < M_; m++) c += s_mk[threadIdx.x * M_ + m];
        s_inv[threadIdx.x] = 1.f / c;
    }
    __syncthreads();

    const float* ab = att + (size_t)b * H_ * L_ * L_;
    for (int c = grp; c < EH; c += 8) {
        int e = c / H_, h = c % H_;
        float acc = 0.f;
#pragma unroll
        for (int m = 0; m < M_; m++) {
            float mk = s_mk[e * M_ + m];
            if (mk > 0.f)
                acc += ab[((size_t)h * L_ + s_row[e * M_ + m]) * L_ + l];
        }
        Et[c * 33 + lane] = acc * s_inv[e];
    }
    __syncthreads();

    float* dst = g_ea + ((size_t)b * L_ + lc * 32) * EH;
    for (int o = threadIdx.x; o < 32 * EH; o += 256) {
        int ll = o / EH, c = o % EH;
        dst[o] = Et[c * 33 + ll];
    }
}

// ===========================================================================
// K2b: transpose + bf16-split SO -> g_Bhi/g_Blo [b, d, l]
// ===========================================================================
__global__ void k_transpose(const float* __restrict__ so) {
    __shared__ float t[32][33];
    int b  = blockIdx.z;
    int l0 = blockIdx.x * 32;
    int d0 = blockIdx.y * 32;
    int tx = threadIdx.x, ty = threadIdx.y;

#pragma unroll
    for (int i = 0; i < 4; i++) {
        int l = l0 + ty + i * 8;
        t[ty + i * 8][tx] = so[((size_t)b * L_ + l) * D_ + d0 + tx];
    }
    __syncthreads();
#pragma unroll
    for (int i = 0; i < 4; i++) {
        int d = d0 + ty + i * 8;
        float v = t[tx][ty + i * 8];
        __nv_bfloat16 hi = __float2bfloat16(v);
        __nv_bfloat16 lo = __float2bfloat16(v - __bfloat162float(hi));
        size_t o = ((size_t)(b * D_ + d)) * L_ + l0 + tx;
        g_Bhi[o] = hi;
        g_Blo[o] = lo;
    }
}

// ===========================================================================
// K3: Gram pair attention.  grid = (32 l-chunks, B), block = 256.
// X[p, l] = sum_h E[l,i,h]*E[l,j,h] computed from a SMEM-resident E tile.
// Emits bf16 hi/lo X rows + deterministic per-chunk partial sums.
// ===========================================================================
__global__ __launch_bounds__(256)
void k_gram() {
    extern __shared__ float El[];              // 32 x 512 floats
    int lc = blockIdx.x, b = blockIdx.y;

    const float* src = g_ea + ((size_t)b * L_ + lc * 32) * EH;
    for (int o = threadIdx.x; o < 32 * EH; o += 256) {
        int l = o / EH, c = o % EH;
        El[l * 512 + c] = src[o];
    }
    __syncthreads();

    for (int p = threadIdx.x; p < NPU; p += 256) {
        int i = 0, rem = p;
        while (rem >= NE_ - 1 - i) { rem -= NE_ - 1 - i; i++; }
        int j = i + 1 + rem;

        __nv_bfloat16 hb[32], lb[32];
        float lsum = 0.f;
#pragma unroll
        for (int l = 0; l < 32; l++) {
            const float4* a4 = (const float4*)&El[l * 512 + i * H_];
            const float4* c4 = (const float4*)&El[l * 512 + j * H_];
            float4 a0 = a4[0], a1 = a4[1], a2 = a4[2];
            float4 c0 = c4[0], c1 = c4[1], c2 = c4[2];
            float x = a0.x*c0.x + a0.y*c0.y + a0.z*c0.z + a0.w*c0.w
                    + a1.x*c1.x + a1.y*c1.y + a1.z*c1.z + a1.w*c1.w
                    + a2.x*c2.x + a2.y*c2.y + a2.z*c2.z + a2.w*c2.w;
            __nv_bfloat16 h = __float2bfloat16(x);
            hb[l] = h;
            lb[l] = __float2bfloat16(x - __bfloat162float(h));
            lsum += x;
        }
        size_t rowb = ((size_t)(b * MP + p)) * L_ + lc * 32;
        const uint4* h4 = (const uint4*)hb;
        const uint4* l4 = (const uint4*)lb;
#pragma unroll
        for (int c = 0; c < 4; c++) {
            *(uint4*)&g_Xhi[rowb + c * 8] = h4[c];
            *(uint4*)&g_Xlo[rowb + c * 8] = l4[c];
        }
        g_xpart[(b * 32 + lc) * NPU + p] = lsum;
    }
}

// K3b: deterministic scale finalize
__global__ void k_finalize() {
    int t = blockIdx.x * 256 + threadIdx.x;
    if (t >= B_ * NPU) return;
    int b = t / NPU, p = t % NPU;
    float s = 0.f;
#pragma unroll
    for (int c = 0; c < 32; c++) s += g_xpart[(b * 32 + c) * NPU + p];
    g_scale[t] = 1.f / (s + EPS_H);
}

// ===========================================================================
// K4: mma.sync bf16x3 GEMM, cp.async double-buffered (unchanged from R7).
//     CTA tile 128x64, BK=32, 256 thr (8 warps = 4m x 2n), 2 CTAs/SM.
// ===========================================================================
#define TS2    80
#define STG    30720
#define SB_OFF 20480
#define CSTRIDE 68
#define SM_TOT (2*STG)

__global__ __launch_bounds__(256, 2)
void k_gemm_mma(float* __restrict__ out) {
    extern __shared__ char smem[];
    uint32_t sb = smem_u32(smem);

    int tid = threadIdx.x;
    int wid = tid >> 5, lane = tid & 31;
    int gid = lane >> 2, tig = lane & 3;
    int wm = wid >> 1, wn = wid & 1;
    int b  = blockIdx.z;
    int m0 = blockIdx.y * 128;
    int n0 = blockIdx.x * 64;

    const uint4* Ahi = (const uint4*)g_Xhi;
    const uint4* Alo = (const uint4*)g_Xlo;
    const uint4* Bhi = (const uint4*)g_Bhi;
    const uint4* Blo = (const uint4*)g_Blo;
    int arow0 = (b * MP + m0) * 128;
    int brow0 = (b * D_ + n0) * 128;

    int b_row = tid >> 2, b_seg = tid & 3;

    int sub = lane >> 3, lrow = lane & 7;
    int a_r = wm * 32 + lrow + (sub & 1) * 8;
    int a_k = (sub >> 1) * 8;
    int b_r = wn * 32 + lrow + (sub >> 1) * 8;
    int b_k = (sub & 1) * 8;

    float acc[2][4][4];
#pragma unroll
    for (int mt = 0; mt < 2; mt++)
#pragma unroll
        for (int nt = 0; nt < 4; nt++)
#pragma unroll
            for (int r = 0; r < 4; r++) acc[mt][nt][r] = 0.f;

#define LOAD_STAGE(it, stg) do {                                            \
    uint32_t s0 = sb + (stg) * STG;                                         \
    _Pragma("unroll")                                                       \
    for (int c = 0; c < 2; c++) {                                           \
        int idx = tid + c * 256;                                            \
        int row = idx >> 2, seg = idx & 3;                                  \
        int gi = arow0 + row * 128 + (it) * 4 + seg;                        \
        uint32_t sa = s0 + row * TS2 + seg * 16;                            \
        cpa16(sa,         Ahi + gi);                                        \
        cpa16(sa + 10240, Alo + gi);                                        \
    }                                                                       \
    {                                                                       \
        int gi = brow0 + b_row * 128 + (it) * 4 + b_seg;                    \
        uint32_t sB = s0 + SB_OFF + b_row * TS2 + b_seg * 16;               \
        cpa16(sB,        Bhi + gi);                                         \
        cpa16(sB + 5120, Blo + gi);                                         \
    }                                                                       \
} while (0)

    LOAD_STAGE(0, 0); CP_COMMIT();
    LOAD_STAGE(1, 1); CP_COMMIT();

    for (int it = 0; it < 32; it++) {
        if (it + 1 < 32) { CP_WAIT(1); } else { CP_WAIT(0); }
        __syncthreads();

        uint32_t s0 = sb + (it & 1) * STG;
#pragma unroll
        for (int ks = 0; ks < 2; ks++) {
            uint32_t ah[2][4], al[2][4], bh[4][2], bl[4][2];
            int kofs = (ks * 16 + a_k) * 2;
#pragma unroll
            for (int mt = 0; mt < 2; mt++) {
                uint32_t ad = s0 + (a_r + mt * 16) * TS2 + kofs;
                ldm_x4(ah[mt], ad);
                ldm_x4(al[mt], ad + 10240);
            }
            int kofsb = (ks * 16 + b_k) * 2;
#pragma unroll
            for (int np = 0; np < 2; np++) {
                uint32_t bd = s0 + SB_OFF + (b_r + np * 16) * TS2 + kofsb;
                uint32_t t4[4];
                ldm_x4(t4, bd);
                bh[np*2][0] = t4[0]; bh[np*2][1] = t4[1];
                bh[np*2+1][0] = t4[2]; bh[np*2+1][1] = t4[3];
                ldm_x4(t4, bd + 5120);
                bl[np*2][0] = t4[0]; bl[np*2][1] = t4[1];
                bl[np*2+1][0] = t4[2]; bl[np*2+1][1] = t4[3];
            }
#pragma unroll
            for (int mt = 0; mt < 2; mt++)
#pragma unroll
                for (int nt = 0; nt < 4; nt++) {
                    mma_bf16(acc[mt][nt], ah[mt], bh[nt]);
                    mma_bf16(acc[mt][nt], ah[mt], bl[nt]);
                    mma_bf16(acc[mt][nt], al[mt], bh[nt]);
                }
        }
        __syncthreads();
        if (it + 2 < 32) { LOAD_STAGE(it + 2, it & 1); CP_COMMIT(); }
    }

    // -------- epilogue --------
    __shared__ float s_sc[128];
    __shared__ int   s_p1[128], s_p2[128];

    float* C = (float*)smem;
#pragma unroll
    for (int mt = 0; mt < 2; mt++) {
        int rm = wm * 32 + mt * 16 + gid;
#pragma unroll
        for (int nt = 0; nt < 4; nt++) {
            int cn = wn * 32 + nt * 8 + tig * 2;
            *(float2*)&C[rm * CSTRIDE + cn]       = make_float2(acc[mt][nt][0], acc[mt][nt][1]);
            *(float2*)&C[(rm + 8) * CSTRIDE + cn] = make_float2(acc[mt][nt][2], acc[mt][nt][3]);
        }
    }
    if (tid < 128) {
        int q = m0 + tid;
        if (q < NPU) {
            s_sc[tid] = g_scale[b * NPU + q];
            int i = 0, rem = q;
            while (rem >= NE_ - 1 - i) { rem -= NE_ - 1 - i; i++; }
            int j = i + 1 + rem;
            s_p1[tid] = g_p2p[(b * NE_ + i) * NE_ + j];
            s_p2[tid] = g_p2p[(b * NE_ + j) * NE_ + i];
        }
    }
    __syncthreads();

    int r    = tid >> 1;
    int half = (tid & 1) * 32;
    int q = m0 + r;
    if (q < NPU) {
        float sc = s_sc[r];
        float* ht = out + (size_t)B_ * NE_ * D_;
        size_t o1 = ((size_t)(b * P_ + s_p1[r])) * D_ + n0 + half;
        size_t o2 = ((size_t)(b * P_ + s_p2[r])) * D_ + n0 + half;
        const float* crow = &C[r * CSTRIDE + half];
#pragma unroll
        for (int c = 0; c < 32; c += 4) {
            float4 v = make_float4(crow[c] * sc, crow[c + 1] * sc,
                                   crow[c + 2] * sc, crow[c + 3] * sc);
            *(float4*)&ht[o1 + c] = v;
            *(float4*)&ht[o2 + c] = v;
        }
    }
}

// ===========================================================================
extern "C" void kernel_launch(void* const* d_in, const int* in_sizes, int n_in,
                              void* d_out, int out_size) {
    const float* so   = nullptr;
    const float* att  = nullptr;
    const float* mask = nullptr;
    const int*   posw = nullptr;
    const int*   htsw = nullptr;

    for (int k = 0; k < n_in; k++) {
        int sz = in_sizes[k];
        if      (sz == SZ_SO)  so   = (const float*)d_in[k];
        else if (sz == SZ_ATT) att  = (const float*)d_in[k];
        else if (sz == SZ_HTS) htsw = (const int*)d_in[k];
        else if (sz == SZ_MSK) {
            if (!mask) mask = (const float*)d_in[k];
            else       posw = (const int*)d_in[k];
        }
    }
    float* out = (float*)d_out;

    const int EA_SMEM   = EH * 33 * 4;       // 66528
    const int GRAM_SMEM = 32 * 512 * 4;      // 65536
    cudaFuncSetAttribute(k_gemm_mma,
                         cudaFuncAttributeMaxDynamicSharedMemorySize, SM_TOT);
    cudaFuncSetAttribute(k_entity_att,
                         cudaFuncAttributeMaxDynamicSharedMemorySize, EA_SMEM);
    cudaFuncSetAttribute(k_gram,
                         cudaFuncAttributeMaxDynamicSharedMemorySize, GRAM_SMEM);

    k_prep<<<1, 1024>>>(posw, htsw);
    k_entity_embed<<<B_ * NE_, D_>>>(so, mask, out);
    {
        dim3 g(L_ / 32, D_ / 32, B_);
        dim3 t(32, 8);
        k_transpose<<<g, t>>>(so);
    }
    {
        dim3 g(32, B_);
        k_entity_att<<<g, 256, EA_SMEM>>>(att, mask);
        k_gram<<<g, 256, GRAM_SMEM>>>();
    }
    k_finalize<<<(B_ * NPU + 255) / 256, 256>>>();

    dim3 grid(D_ / 64, MP / 128, B_);
    k_gemm_mma<<<grid, 256, SM_TOT>>>(out);
}

// round 10
// speedup vs baseline: 1.4574x; 1.4574x over previous
#include <cuda_runtime.h>
#include <cuda_bf16.h>
#include <cstdint>
#include <math.h>

// Problem constants
#define B_  4
#define L_  1024
#define D_  768
#define H_  12
#define NE_ 42
#define M_  8
#define P_  (NE_*(NE_-1))      // 1722 ordered pairs
#define NPU 861                // unordered pairs (i<j)
#define MP  896                // NPU padded to 128
#define EPS_H 1.2e-4f
#define EH  (NE_*H_)           // 504
#define LC  16                 // l-chunk for gram
#define NLC (L_/LC)            // 64 chunks

// Input element counts
#define SZ_SO   (B_*L_*D_)
#define SZ_ATT  (B_*H_*L_*L_)
#define SZ_HTS  (B_*P_*2)
#define SZ_MSK  (B_*NE_*M_)

// Scratch (zero-init; pad rows >= NPU stay zero)
__device__ float          g_ea[B_*H_*NE_*L_];     // E [b, h, e, l]
__device__ __nv_bfloat16  g_Xhi[B_*MP*L_];
__device__ __nv_bfloat16  g_Xlo[B_*MP*L_];
__device__ __nv_bfloat16  g_Bhi[B_*D_*L_];
__device__ __nv_bfloat16  g_Blo[B_*D_*L_];
__device__ float          g_xpart[B_*NLC*NPU];    // per-l-chunk partial sums
__device__ float          g_scale[B_*NPU];
__device__ int            g_p2p[B_*NE_*NE_];
__device__ int            g_pos[B_*NE_*M_];
__device__ int            g_ht [B_*P_*2];

// ===========================================================================
// PTX helpers (baseline ISA only — sm_103 non-'a' target: no tcgen05)
// ===========================================================================
__device__ __forceinline__ uint32_t smem_u32(const void* p) {
    uint32_t a;
    asm("{ .reg .u64 t; cvta.to.shared.u64 t, %1; cvt.u32.u64 %0, t; }"
        : "=r"(a) : "l"(p));
    return a;
}
__device__ __forceinline__ void ldm_x4(uint32_t* r, uint32_t addr) {
    asm volatile("ldmatrix.sync.aligned.m8n8.x4.shared.b16 {%0,%1,%2,%3}, [%4];"
        : "=r"(r[0]), "=r"(r[1]), "=r"(r[2]), "=r"(r[3]) : "r"(addr));
}
__device__ __forceinline__ void mma_bf16(float* d, const uint32_t* a,
                                         const uint32_t* b) {
    asm volatile("mma.sync.aligned.m16n8k16.row.col.f32.bf16.bf16.f32 "
        "{%0,%1,%2,%3}, {%4,%5,%6,%7}, {%8,%9}, {%0,%1,%2,%3};"
        : "+f"(d[0]), "+f"(d[1]), "+f"(d[2]), "+f"(d[3])
        : "r"(a[0]), "r"(a[1]), "r"(a[2]), "r"(a[3]), "r"(b[0]), "r"(b[1]));
}
__device__ __forceinline__ void cpa16(uint32_t s, const void* g) {
    asm volatile("cp.async.cg.shared.global [%0], [%1], 16;" :: "r"(s), "l"(g));
}
#define CP_COMMIT() asm volatile("cp.async.commit_group;" ::: "memory")
#define CP_WAIT(n)  asm volatile("cp.async.wait_group %0;" :: "n"(n) : "memory")

// ===========================================================================
// K0: int width detect + convert + p2p map (one block)
// ===========================================================================
__global__ void k_prep(const int* __restrict__ posw, const int* __restrict__ htsw) {
    __shared__ int s_pos64, s_hts64;
    if (threadIdx.x == 0) {
        int nz = 0;
        for (int w = 1; w < 33; w += 2) nz |= posw[w];
        s_pos64 = (nz == 0) ? 1 : 0;
        nz = 0;
        for (int w = 1; w < 33; w += 2) nz |= htsw[w];
        s_hts64 = (nz == 0) ? 1 : 0;
    }
    __syncthreads();
    int sp = s_pos64 ? 2 : 1;
    for (int t = threadIdx.x; t < B_*NE_*M_; t += blockDim.x)
        g_pos[t] = posw[(size_t)t * sp] + 1;          // fold +OFFSET
    int sh = s_hts64 ? 2 : 1;
    for (int t = threadIdx.x; t < B_*P_*2; t += blockDim.x)
        g_ht[t] = htsw[(size_t)t * sh];
    __syncthreads();
    for (int t = threadIdx.x; t < B_*P_; t += blockDim.x) {
        int b = t / P_;
        int i = g_ht[(size_t)t * 2 + 0];
        int j = g_ht[(size_t)t * 2 + 1];
        g_p2p[(b * NE_ + i) * NE_ + j] = t - b * P_;
    }
}

// ===========================================================================
// K1: entity_embed  (grid = B*NE, block = D)
// ===========================================================================
__global__ void k_entity_embed(const float* __restrict__ so,
                               const float* __restrict__ mask,
                               float* __restrict__ out_ee) {
    int be = blockIdx.x;
    int b = be / NE_;
    int d = threadIdx.x;

    __shared__ int   s_row[M_];
    __shared__ float s_mk[M_];
    if (threadIdx.x < M_) {
        s_mk[threadIdx.x]  = mask[(size_t)be * M_ + threadIdx.x];
        s_row[threadIdx.x] = g_pos[be * M_ + threadIdx.x];
    }
    __syncthreads();

    float v[M_];
    float mx = -INFINITY;
#pragma unroll
    for (int m = 0; m < M_; m++) {
        if (s_mk[m] > 0.f) {
            v[m] = so[((size_t)b * L_ + s_row[m]) * D_ + d];
            mx = fmaxf(mx, v[m]);
        } else v[m] = -INFINITY;
    }
    float s = 0.f;
#pragma unroll
    for (int m = 0; m < M_; m++) s += __expf(v[m] - mx);
    out_ee[(size_t)be * D_ + d] = logf(s) + mx;
}

// ===========================================================================
// K2: entity_att — R7 proven form.  grid = B*NE*H (2016), block = 256.
// Writes g_ea [b, h, e, l], float4 coalesced.  ~11 us, DRAM-bound.
// ===========================================================================
__global__ __launch_bounds__(256)
void k_entity_att(const float* __restrict__ att,
                  const float* __restrict__ mask) {
    int id = blockIdx.x;
    int h  = id % H_;
    int be = id / H_;
    int b  = be / NE_;
    int e  = be % NE_;

    __shared__ int   s_row[M_];
    __shared__ float s_mk[M_];
    if (threadIdx.x < M_) {
        s_mk[threadIdx.x]  = mask[(size_t)be * M_ + threadIdx.x];
        s_row[threadIdx.x] = g_pos[be * M_ + threadIdx.x];
    }
    __syncthreads();

    float cnt = 0.f;
#pragma unroll
    for (int m = 0; m < M_; m++) cnt += s_mk[m];
    float inv = 1.f / cnt;

    const float4* a4 = (const float4*)(att + ((size_t)(b * H_ + h)) * L_ * L_);
    float4* e4 = (float4*)(g_ea + ((size_t)((b * H_ + h) * NE_ + e)) * L_);

    int t = threadIdx.x;
    float4 acc = make_float4(0.f, 0.f, 0.f, 0.f);
#pragma unroll
    for (int m = 0; m < M_; m++) {
        if (s_mk[m] > 0.f) {
            float4 v = a4[(size_t)s_row[m] * 256 + t];
            acc.x += v.x; acc.y += v.y; acc.z += v.z; acc.w += v.w;
        }
    }
    acc.x *= inv; acc.y *= inv; acc.z *= inv; acc.w *= inv;
    e4[t] = acc;
}

// ===========================================================================
// K2b: transpose + bf16-split SO -> g_Bhi/g_Blo [b, d, l]
// ===========================================================================
__global__ void k_transpose(const float* __restrict__ so) {
    __shared__ float t[32][33];
    int b  = blockIdx.z;
    int l0 = blockIdx.x * 32;
    int d0 = blockIdx.y * 32;
    int tx = threadIdx.x, ty = threadIdx.y;

#pragma unroll
    for (int i = 0; i < 4; i++) {
        int l = l0 + ty + i * 8;
        t[ty + i * 8][tx] = so[((size_t)b * L_ + l) * D_ + d0 + tx];
    }
    __syncthreads();
#pragma unroll
    for (int i = 0; i < 4; i++) {
        int d = d0 + ty + i * 8;
        float v = t[tx][ty + i * 8];
        __nv_bfloat16 hi = __float2bfloat16(v);
        __nv_bfloat16 lo = __float2bfloat16(v - __bfloat162float(hi));
        size_t o = ((size_t)(b * D_ + d)) * L_ + l0 + tx;
        g_Bhi[o] = hi;
        g_Blo[o] = lo;
    }
}

// ===========================================================================
// K3: Gram pair attention v2 — 16-l chunks for launch-shape health.
// grid = (64, B) = 256 blocks, 32 KB static smem (>=2 CTAs/SM).
// Fill: read E channels (64B segs) from [b,h,e,l], reorder to El[l][e*12+h].
// Compute: X[p,l] = sum_h Ei*Ej via 6 float4 smem loads per (p,l).
// ===========================================================================
__global__ __launch_bounds__(256)
void k_gram() {
    __shared__ float El[LC * 512];            // 32 KB
    int lc = blockIdx.x, b = blockIdx.y;
    int l0 = lc * LC;

    // ---- fill (reorder [h,e,l-seg] -> El[l][e*12+h]) ----
    for (int o = threadIdx.x; o < EH * (LC / 4); o += 256) {
        int c = o / (LC / 4), part = o % (LC / 4);
        int e = c / H_, h = c % H_;
        const float4 v = *(const float4*)(g_ea
            + ((size_t)((b * H_ + h) * NE_ + e)) * L_ + l0 + part * 4);
        El[(part * 4 + 0) * 512 + c] = v.x;
        El[(part * 4 + 1) * 512 + c] = v.y;
        El[(part * 4 + 2) * 512 + c] = v.z;
        El[(part * 4 + 3) * 512 + c] = v.w;
    }
    __syncthreads();

    // ---- pairs ----
    for (int p = threadIdx.x; p < NPU; p += 256) {
        int i = 0, rem = p;
        while (rem >= NE_ - 1 - i) { rem -= NE_ - 1 - i; i++; }
        int j = i + 1 + rem;

        alignas(16) __nv_bfloat16 hb[LC];
        alignas(16) __nv_bfloat16 lb[LC];
        float lsum = 0.f;
#pragma unroll
        for (int l = 0; l < LC; l++) {
            const float4* a4 = (const float4*)&El[l * 512 + i * H_];
            const float4* c4 = (const float4*)&El[l * 512 + j * H_];
            float4 a0 = a4[0], a1 = a4[1], a2 = a4[2];
            float4 c0 = c4[0], c1 = c4[1], c2 = c4[2];
            float x = a0.x*c0.x + a0.y*c0.y + a0.z*c0.z + a0.w*c0.w
                    + a1.x*c1.x + a1.y*c1.y + a1.z*c1.z + a1.w*c1.w
                    + a2.x*c2.x + a2.y*c2.y + a2.z*c2.z + a2.w*c2.w;
            __nv_bfloat16 h = __float2bfloat16(x);
            hb[l] = h;
            lb[l] = __float2bfloat16(x - __bfloat162float(h));
            lsum += x;
        }
        size_t rowb = ((size_t)(b * MP + p)) * L_ + l0;
        const uint4* h4 = (const uint4*)hb;
        const uint4* l4 = (const uint4*)lb;
        *(uint4*)&g_Xhi[rowb]     = h4[0];
        *(uint4*)&g_Xhi[rowb + 8] = h4[1];
        *(uint4*)&g_Xlo[rowb]     = l4[0];
        *(uint4*)&g_Xlo[rowb + 8] = l4[1];
        g_xpart[(b * NLC + lc) * NPU + p] = lsum;
    }
}

// K3b: deterministic scale finalize
__global__ void k_finalize() {
    int t = blockIdx.x * 256 + threadIdx.x;
    if (t >= B_ * NPU) return;
    int b = t / NPU, p = t % NPU;
    float s = 0.f;
#pragma unroll
    for (int c = 0; c < NLC; c++) s += g_xpart[(b * NLC + c) * NPU + p];
    g_scale[t] = 1.f / (s + EPS_H);
}

// ===========================================================================
// K4: mma.sync bf16x3 GEMM, cp.async double-buffered (R7 config, 131us run).
//     CTA tile 128x64, BK=32, 256 thr (8 warps = 4m x 2n), 2 CTAs/SM.
// ===========================================================================
#define TS2    80
#define STG    30720
#define SB_OFF 20480
#define CSTRIDE 68
#define SM_TOT (2*STG)

__global__ __launch_bounds__(256, 2)
void k_gemm_mma(float* __restrict__ out) {
    extern __shared__ char smem[];
    uint32_t sb = smem_u32(smem);

    int tid = threadIdx.x;
    int wid = tid >> 5, lane = tid & 31;
    int gid = lane >> 2, tig = lane & 3;
    int wm = wid >> 1, wn = wid & 1;
    int b  = blockIdx.z;
    int m0 = blockIdx.y * 128;
    int n0 = blockIdx.x * 64;

    const uint4* Ahi = (const uint4*)g_Xhi;
    const uint4* Alo = (const uint4*)g_Xlo;
    const uint4* Bhi = (const uint4*)g_Bhi;
    const uint4* Blo = (const uint4*)g_Blo;
    int arow0 = (b * MP + m0) * 128;
    int brow0 = (b * D_ + n0) * 128;

    int b_row = tid >> 2, b_seg = tid & 3;

    int sub = lane >> 3, lrow = lane & 7;
    int a_r = wm * 32 + lrow + (sub & 1) * 8;
    int a_k = (sub >> 1) * 8;
    int b_r = wn * 32 + lrow + (sub >> 1) * 8;
    int b_k = (sub & 1) * 8;

    float acc[2][4][4];
#pragma unroll
    for (int mt = 0; mt < 2; mt++)
#pragma unroll
        for (int nt = 0; nt < 4; nt++)
#pragma unroll
            for (int r = 0; r < 4; r++) acc[mt][nt][r] = 0.f;

#define LOAD_STAGE(it, stg) do {                                            \
    uint32_t s0 = sb + (stg) * STG;                                         \
    _Pragma("unroll")                                                       \
    for (int c = 0; c < 2; c++) {                                           \
        int idx = tid + c * 256;                                            \
        int row = idx >> 2, seg = idx & 3;                                  \
        int gi = arow0 + row * 128 + (it) * 4 + seg;                        \
        uint32_t sa = s0 + row * TS2 + seg * 16;                            \
        cpa16(sa,         Ahi + gi);                                        \
        cpa16(sa + 10240, Alo + gi);                                        \
    }                                                                       \
    {                                                                       \
        int gi = brow0 + b_row * 128 + (it) * 4 + b_seg;                    \
        uint32_t sB = s0 + SB_OFF + b_row * TS2 + b_seg * 16;               \
        cpa16(sB,        Bhi + gi);                                         \
        cpa16(sB + 5120, Blo + gi);                                         \
    }                                                                       \
} while (0)

    LOAD_STAGE(0, 0); CP_COMMIT();
    LOAD_STAGE(1, 1); CP_COMMIT();

    for (int it = 0; it < 32; it++) {
        if (it + 1 < 32) { CP_WAIT(1); } else { CP_WAIT(0); }
        __syncthreads();

        uint32_t s0 = sb + (it & 1) * STG;
#pragma unroll
        for (int ks = 0; ks < 2; ks++) {
            uint32_t ah[2][4], al[2][4], bh[4][2], bl[4][2];
            int kofs = (ks * 16 + a_k) * 2;
#pragma unroll
            for (int mt = 0; mt < 2; mt++) {
                uint32_t ad = s0 + (a_r + mt * 16) * TS2 + kofs;
                ldm_x4(ah[mt], ad);
                ldm_x4(al[mt], ad + 10240);
            }
            int kofsb = (ks * 16 + b_k) * 2;
#pragma unroll
            for (int np = 0; np < 2; np++) {
                uint32_t bd = s0 + SB_OFF + (b_r + np * 16) * TS2 + kofsb;
                uint32_t t4[4];
                ldm_x4(t4, bd);
                bh[np*2][0] = t4[0]; bh[np*2][1] = t4[1];
                bh[np*2+1][0] = t4[2]; bh[np*2+1][1] = t4[3];
                ldm_x4(t4, bd + 5120);
                bl[np*2][0] = t4[0]; bl[np*2][1] = t4[1];
                bl[np*2+1][0] = t4[2]; bl[np*2+1][1] = t4[3];
            }
#pragma unroll
            for (int mt = 0; mt < 2; mt++)
#pragma unroll
                for (int nt = 0; nt < 4; nt++) {
                    mma_bf16(acc[mt][nt], ah[mt], bh[nt]);
                    mma_bf16(acc[mt][nt], ah[mt], bl[nt]);
                    mma_bf16(acc[mt][nt], al[mt], bh[nt]);
                }
        }
        __syncthreads();
        if (it + 2 < 32) { LOAD_STAGE(it + 2, it & 1); CP_COMMIT(); }
    }

    // -------- epilogue --------
    __shared__ float s_sc[128];
    __shared__ int   s_p1[128], s_p2[128];

    float* C = (float*)smem;
#pragma unroll
    for (int mt = 0; mt < 2; mt++) {
        int rm = wm * 32 + mt * 16 + gid;
#pragma unroll
        for (int nt = 0; nt < 4; nt++) {
            int cn = wn * 32 + nt * 8 + tig * 2;
            *(float2*)&C[rm * CSTRIDE + cn]       = make_float2(acc[mt][nt][0], acc[mt][nt][1]);
            *(float2*)&C[(rm + 8) * CSTRIDE + cn] = make_float2(acc[mt][nt][2], acc[mt][nt][3]);
        }
    }
    if (tid < 128) {
        int q = m0 + tid;
        if (q < NPU) {
            s_sc[tid] = g_scale[b * NPU + q];
            int i = 0, rem = q;
            while (rem >= NE_ - 1 - i) { rem -= NE_ - 1 - i; i++; }
            int j = i + 1 + rem;
            s_p1[tid] = g_p2p[(b * NE_ + i) * NE_ + j];
            s_p2[tid] = g_p2p[(b * NE_ + j) * NE_ + i];
        }
    }
    __syncthreads();

    int r    = tid >> 1;
    int half = (tid & 1) * 32;
    int q = m0 + r;
    if (q < NPU) {
        float sc = s_sc[r];
        float* ht = out + (size_t)B_ * NE_ * D_;
        size_t o1 = ((size_t)(b * P_ + s_p1[r])) * D_ + n0 + half;
        size_t o2 = ((size_t)(b * P_ + s_p2[r])) * D_ + n0 + half;
        const float* crow = &C[r * CSTRIDE + half];
#pragma unroll
        for (int c = 0; c < 32; c += 4) {
            float4 v = make_float4(crow[c] * sc, crow[c + 1] * sc,
                                   crow[c + 2] * sc, crow[c + 3] * sc);
            *(float4*)&ht[o1 + c] = v;
            *(float4*)&ht[o2 + c] = v;
        }
    }
}

// ===========================================================================
extern "C" void kernel_launch(void* const* d_in, const int* in_sizes, int n_in,
                              void* d_out, int out_size) {
    const float* so   = nullptr;
    const float* att  = nullptr;
    const float* mask = nullptr;
    const int*   posw = nullptr;
    const int*   htsw = nullptr;

    for (int k = 0; k < n_in; k++) {
        int sz = in_sizes[k];
        if      (sz == SZ_SO)  so   = (const float*)d_in[k];
        else if (sz == SZ_ATT) att  = (const float*)d_in[k];
        else if (sz == SZ_HTS) htsw = (const int*)d_in[k];
        else if (sz == SZ_MSK) {
            if (!mask) mask = (const float*)d_in[k];
            else       posw = (const int*)d_in[k];
        }
    }
    float* out = (float*)d_out;

    cudaFuncSetAttribute(k_gemm_mma,
                         cudaFuncAttributeMaxDynamicSharedMemorySize, SM_TOT);

    k_prep<<<1, 1024>>>(posw, htsw);
    k_entity_embed<<<B_ * NE_, D_>>>(so, mask, out);
    {
        dim3 g(L_ / 32, D_ / 32, B_);
        dim3 t(32, 8);
        k_transpose<<<g, t>>>(so);
    }
    k_entity_att<<<B_ * NE_ * H_, 256>>>(att, mask);
    {
        dim3 g(NLC, B_);
        k_gram<<<g, 256>>>();
    }
    k_finalize<<<(B_ * NPU + 255) / 256, 256>>>();

    dim3 grid(D_ / 64, MP / 128, B_);
    k_gemm_mma<<<grid, 256, SM_TOT>>>(out);
}

// round 14
// speedup vs baseline: 2.1337x; 1.4640x over previous
#include <cuda_runtime.h>
#include <cuda_fp16.h>
#include <cstdint>
#include <math.h>

// Problem constants
#define B_  4
#define L_  1024
#define D_  768
#define H_  12
#define NE_ 42
#define M_  8
#define P_  (NE_*(NE_-1))      // 1722 ordered pairs
#define NPU 861                // unordered pairs (i<j)
#define MP  896                // NPU padded to 128
#define EPS_H 1.2e-4f
#define EH  (NE_*H_)           // 504
#define LC  16                 // l-chunk for gram
#define NLC (L_/LC)            // 64 chunks

// Input element counts
#define SZ_SO   (B_*L_*D_)
#define SZ_ATT  (B_*H_*L_*L_)
#define SZ_HTS  (B_*P_*2)
#define SZ_MSK  (B_*NE_*M_)

// Scratch (zero-init; pad rows >= NPU stay zero)
__device__ float   g_ea[B_*H_*NE_*L_];     // E [b, h, e, l]
__device__ __half  g_X[B_*MP*L_];          // pair att fp16 [b,q,l]
__device__ __half  g_B[B_*D_*L_];          // SO^T fp16 [b,d,l]
__device__ float   g_xpart[B_*NLC*NPU];
__device__ float   g_scale[B_*NPU];
__device__ int     g_p2p[B_*NE_*NE_];
__device__ int     g_pos[B_*NE_*M_];
__device__ int     g_ht [B_*P_*2];

// ===========================================================================
// PTX helpers (baseline ISA only — sm_103 non-'a' target: no tcgen05)
// ===========================================================================
__device__ __forceinline__ uint32_t smem_u32(const void* p) {
    uint32_t a;
    asm("{ .reg .u64 t; cvta.to.shared.u64 t, %1; cvt.u32.u64 %0, t; }"
        : "=r"(a) : "l"(p));
    return a;
}
__device__ __forceinline__ void ldm_x4(uint32_t* r, uint32_t addr) {
    asm volatile("ldmatrix.sync.aligned.m8n8.x4.shared.b16 {%0,%1,%2,%3}, [%4];"
        : "=r"(r[0]), "=r"(r[1]), "=r"(r[2]), "=r"(r[3]) : "r"(addr));
}
__device__ __forceinline__ void mma_f16(float* d, const uint32_t* a,
                                        const uint32_t* b) {
    asm volatile("mma.sync.aligned.m16n8k16.row.col.f32.f16.f16.f32 "
        "{%0,%1,%2,%3}, {%4,%5,%6,%7}, {%8,%9}, {%0,%1,%2,%3};"
        : "+f"(d[0]), "+f"(d[1]), "+f"(d[2]), "+f"(d[3])
        : "r"(a[0]), "r"(a[1]), "r"(a[2]), "r"(a[3]), "r"(b[0]), "r"(b[1]));
}
__device__ __forceinline__ void cpa16(uint32_t s, const void* g) {
    asm volatile("cp.async.cg.shared.global [%0], [%1], 16;" :: "r"(s), "l"(g));
}
#define CP_COMMIT() asm volatile("cp.async.commit_group;" ::: "memory")
#define CP_WAIT(n)  asm volatile("cp.async.wait_group %0;" :: "n"(n) : "memory")

// ===========================================================================
// K0: int width detect + convert + p2p map (one block)
// ===========================================================================
__global__ void k_prep(const int* __restrict__ posw, const int* __restrict__ htsw) {
    __shared__ int s_pos64, s_hts64;
    if (threadIdx.x == 0) {
        int nz = 0;
        for (int w = 1; w < 33; w += 2) nz |= posw[w];
        s_pos64 = (nz == 0) ? 1 : 0;
        nz = 0;
        for (int w = 1; w < 33; w += 2) nz |= htsw[w];
        s_hts64 = (nz == 0) ? 1 : 0;
    }
    __syncthreads();
    int sp = s_pos64 ? 2 : 1;
    for (int t = threadIdx.x; t < B_*NE_*M_; t += blockDim.x)
        g_pos[t] = posw[(size_t)t * sp] + 1;          // fold +OFFSET
    int sh = s_hts64 ? 2 : 1;
    for (int t = threadIdx.x; t < B_*P_*2; t += blockDim.x)
        g_ht[t] = htsw[(size_t)t * sh];
    __syncthreads();
    for (int t = threadIdx.x; t < B_*P_; t += blockDim.x) {
        int b = t / P_;
        int i = g_ht[(size_t)t * 2 + 0];
        int j = g_ht[(size_t)t * 2 + 1];
        g_p2p[(b * NE_ + i) * NE_ + j] = t - b * P_;
    }
}

// ===========================================================================
// K1: entity_embed  (grid = B*NE, block = D)
// ===========================================================================
__global__ void k_entity_embed(const float* __restrict__ so,
                               const float* __restrict__ mask,
                               float* __restrict__ out_ee) {
    int be = blockIdx.x;
    int b = be / NE_;
    int d = threadIdx.x;

    __shared__ int   s_row[M_];
    __shared__ float s_mk[M_];
    if (threadIdx.x < M_) {
        s_mk[threadIdx.x]  = mask[(size_t)be * M_ + threadIdx.x];
        s_row[threadIdx.x] = g_pos[be * M_ + threadIdx.x];
    }
    __syncthreads();

    float v[M_];
    float mx = -INFINITY;
#pragma unroll
    for (int m = 0; m < M_; m++) {
        if (s_mk[m] > 0.f) {
            v[m] = so[((size_t)b * L_ + s_row[m]) * D_ + d];
            mx = fmaxf(mx, v[m]);
        } else v[m] = -INFINITY;
    }
    float s = 0.f;
#pragma unroll
    for (int m = 0; m < M_; m++) s += __expf(v[m] - mx);
    out_ee[(size_t)be * D_ + d] = logf(s) + mx;
}

// ===========================================================================
// K2: entity_att — proven form.  grid = B*NE*H (2016), block = 256.
// ===========================================================================
__global__ __launch_bounds__(256)
void k_entity_att(const float* __restrict__ att,
                  const float* __restrict__ mask) {
    int id = blockIdx.x;
    int h  = id % H_;
    int be = id / H_;
    int b  = be / NE_;
    int e  = be % NE_;

    __shared__ int   s_row[M_];
    __shared__ float s_mk[M_];
    if (threadIdx.x < M_) {
        s_mk[threadIdx.x]  = mask[(size_t)be * M_ + threadIdx.x];
        s_row[threadIdx.x] = g_pos[be * M_ + threadIdx.x];
    }
    __syncthreads();

    float cnt = 0.f;
#pragma unroll
    for (int m = 0; m < M_; m++) cnt += s_mk[m];
    float inv = 1.f / cnt;

    const float4* a4 = (const float4*)(att + ((size_t)(b * H_ + h)) * L_ * L_);
    float4* e4 = (float4*)(g_ea + ((size_t)((b * H_ + h) * NE_ + e)) * L_);

    int t = threadIdx.x;
    float4 acc = make_float4(0.f, 0.f, 0.f, 0.f);
#pragma unroll
    for (int m = 0; m < M_; m++) {
        if (s_mk[m] > 0.f) {
            float4 v = a4[(size_t)s_row[m] * 256 + t];
            acc.x += v.x; acc.y += v.y; acc.z += v.z; acc.w += v.w;
        }
    }
    acc.x *= inv; acc.y *= inv; acc.z *= inv; acc.w *= inv;
    e4[t] = acc;
}

// ===========================================================================
// K2b: transpose + fp16 SO -> g_B [b, d, l]
// ===========================================================================
__global__ void k_transpose(const float* __restrict__ so) {
    __shared__ float t[32][33];
    int b  = blockIdx.z;
    int l0 = blockIdx.x * 32;
    int d0 = blockIdx.y * 32;
    int tx = threadIdx.x, ty = threadIdx.y;

#pragma unroll
    for (int i = 0; i < 4; i++) {
        int l = l0 + ty + i * 8;
        t[ty + i * 8][tx] = so[((size_t)b * L_ + l) * D_ + d0 + tx];
    }
    __syncthreads();
#pragma unroll
    for (int i = 0; i < 4; i++) {
        int d = d0 + ty + i * 8;
        g_B[((size_t)(b * D_ + d)) * L_ + l0 + tx] = __float2half(t[tx][ty + i * 8]);
    }
}

// ===========================================================================
// K3: Gram pair attention (R10 proven shape).  grid = (64, B), block = 256.
// ===========================================================================
__global__ __launch_bounds__(256)
void k_gram() {
    __shared__ float El[LC * 512];            // 32 KB
    int lc = blockIdx.x, b = blockIdx.y;
    int l0 = lc * LC;

    for (int o = threadIdx.x; o < EH * (LC / 4); o += 256) {
        int c = o / (LC / 4), part = o % (LC / 4);
        int e = c / H_, h = c % H_;
        const float4 v = *(const float4*)(g_ea
            + ((size_t)((b * H_ + h) * NE_ + e)) * L_ + l0 + part * 4);
        El[(part * 4 + 0) * 512 + c] = v.x;
        El[(part * 4 + 1) * 512 + c] = v.y;
        El[(part * 4 + 2) * 512 + c] = v.z;
        El[(part * 4 + 3) * 512 + c] = v.w;
    }
    __syncthreads();

    for (int p = threadIdx.x; p < NPU; p += 256) {
        int i = 0, rem = p;
        while (rem >= NE_ - 1 - i) { rem -= NE_ - 1 - i; i++; }
        int j = i + 1 + rem;

        alignas(16) __half hb[LC];
        float lsum = 0.f;
#pragma unroll
        for (int l = 0; l < LC; l++) {
            const float4* a4 = (const float4*)&El[l * 512 + i * H_];
            const float4* c4 = (const float4*)&El[l * 512 + j * H_];
            float4 a0 = a4[0], a1 = a4[1], a2 = a4[2];
            float4 c0 = c4[0], c1 = c4[1], c2 = c4[2];
            float x = a0.x*c0.x + a0.y*c0.y + a0.z*c0.z + a0.w*c0.w
                    + a1.x*c1.x + a1.y*c1.y + a1.z*c1.z + a1.w*c1.w
                    + a2.x*c2.x + a2.y*c2.y + a2.z*c2.z + a2.w*c2.w;
            hb[l] = __float2half(x);
            lsum += x;
        }
        size_t rowb = ((size_t)(b * MP + p)) * L_ + l0;
        const uint4* h4 = (const uint4*)hb;
        *(uint4*)&g_X[rowb]     = h4[0];
        *(uint4*)&g_X[rowb + 8] = h4[1];
        g_xpart[(b * NLC + lc) * NPU + p] = lsum;
    }
}

// K3b: deterministic scale finalize
__global__ void k_finalize() {
    int t = blockIdx.x * 256 + threadIdx.x;
    if (t >= B_ * NPU) return;
    int b = t / NPU, p = t % NPU;
    float s = 0.f;
#pragma unroll
    for (int c = 0; c < NLC; c++) s += g_xpart[(b * NLC + c) * NPU + p];
    g_scale[t] = 1.f / (s + EPS_H);
}

// ===========================================================================
// K4: single-pass fp16 mma.sync GEMM, 3-stage cp.async pipeline.
//     CTA tile 128(M) x 128(N), BK=32, 256 thr (8 warps = 2m x 4n, 64x32).
//     grid = (D/128=6, MP/128=7, B) = 168 CTAs, 2 CTAs/SM.
// SMEM stage (20480 B): A[128 rows][80B] @0, B[128 rows][80B] @10240.
// 3 stages = 61440.  Epilogue reuses smem as C[128][132] f32 (67584).
// ===========================================================================
#define TS2    80
#define STG    20480
#define SBO    10240
#define CSTRIDE 132
#define SM_TOT (128*CSTRIDE*4)    // 67584

__global__ __launch_bounds__(256, 2)
void k_gemm_mma(float* __restrict__ out) {
    extern __shared__ char smem[];
    uint32_t sb = smem_u32(smem);

    int tid = threadIdx.x;
    int wid = tid >> 5, lane = tid & 31;
    int gid = lane >> 2, tig = lane & 3;
    int wm = wid >> 2, wn = wid & 3;         // 2(m) x 4(n)
    int b  = blockIdx.z;
    int m0 = blockIdx.y * 128;
    int n0 = blockIdx.x * 128;

    const uint4* Ag = (const uint4*)g_X;     // row = 128 uint4 (1024 fp16)
    const uint4* Bg = (const uint4*)g_B;
    int arow0 = (b * MP + m0) * 128;
    int brow0 = (b * D_ + n0) * 128;

    // ldmatrix lane addressing
    int sub = lane >> 3, lrow = lane & 7;
    int a_r = wm * 64 + lrow + (sub & 1) * 8;
    int a_k = (sub >> 1) * 8;
    int b_r = wn * 32 + lrow + (sub >> 1) * 8;
    int b_k = (sub & 1) * 8;

    float acc[4][4][4];
#pragma unroll
    for (int mt = 0; mt < 4; mt++)
#pragma unroll
        for (int nt = 0; nt < 4; nt++)
#pragma unroll
            for (int r = 0; r < 4; r++) acc[mt][nt][r] = 0.f;

#define LOAD_STAGE(it, slot) do {                                           \
    uint32_t s0 = sb + (slot) * STG;                                        \
    _Pragma("unroll")                                                       \
    for (int c = 0; c < 2; c++) {                                           \
        int idx = tid + c * 256;                                            \
        int row = idx >> 2, seg = idx & 3;                                  \
        cpa16(s0 + row * TS2 + seg * 16,                                    \
              Ag + arow0 + row * 128 + (it) * 4 + seg);                     \
        cpa16(s0 + SBO + row * TS2 + seg * 16,                              \
              Bg + brow0 + row * 128 + (it) * 4 + seg);                     \
    }                                                                       \
} while (0)

    LOAD_STAGE(0, 0); CP_COMMIT();
    LOAD_STAGE(1, 1); CP_COMMIT();

    for (int it = 0; it < 32; it++) {
        CP_WAIT(1);
        __syncthreads();
        if (it + 2 < 32) {
            LOAD_STAGE(it + 2, (it + 2) % 3);
            CP_COMMIT();
        }

        uint32_t s0 = sb + (it % 3) * STG;
#pragma unroll
        for (int ks = 0; ks < 2; ks++) {
            uint32_t a[4][4], bb[4][2];
            int kofs = (ks * 16 + a_k) * 2;
#pragma unroll
            for (int mt = 0; mt < 4; mt++)
                ldm_x4(a[mt], s0 + (a_r + mt * 16) * TS2 + kofs);
            int kofsb = (ks * 16 + b_k) * 2;
#pragma unroll
            for (int np = 0; np < 2; np++) {
                uint32_t t4[4];
                ldm_x4(t4, s0 + SBO + (b_r + np * 16) * TS2 + kofsb);
                bb[np*2][0] = t4[0];   bb[np*2][1] = t4[1];
                bb[np*2+1][0] = t4[2]; bb[np*2+1][1] = t4[3];
            }
#pragma unroll
            for (int mt = 0; mt < 4; mt++)
#pragma unroll
                for (int nt = 0; nt < 4; nt++)
                    mma_f16(acc[mt][nt], a[mt], bb[nt]);
        }
    }
    __syncthreads();   // all operand reads done; reuse smem as C

    // -------- epilogue: acc -> SMEM C, scaled dual scatter --------
    __shared__ float s_sc[128];
    __shared__ int   s_p1[128], s_p2[128];

    float* C = (float*)smem;
#pragma unroll
    for (int mt = 0; mt < 4; mt++) {
        int rm = wm * 64 + mt * 16 + gid;
#pragma unroll
        for (int nt = 0; nt < 4; nt++) {
            int cn = wn * 32 + nt * 8 + tig * 2;
            *(float2*)&C[rm * CSTRIDE + cn]       = make_float2(acc[mt][nt][0], acc[mt][nt][1]);
            *(float2*)&C[(rm + 8) * CSTRIDE + cn] = make_float2(acc[mt][nt][2], acc[mt][nt][3]);
        }
    }
    if (tid < 128) {
        int q = m0 + tid;
        if (q < NPU) {
            s_sc[tid] = g_scale[b * NPU + q];
            int i = 0, rem = q;
            while (rem >= NE_ - 1 - i) { rem -= NE_ - 1 - i; i++; }
            int j = i + 1 + rem;
            s_p1[tid] = g_p2p[(b * NE_ + i) * NE_ + j];
            s_p2[tid] = g_p2p[(b * NE_ + j) * NE_ + i];
        }
    }
    __syncthreads();

    int r    = tid >> 1;
    int half = (tid & 1) * 64;
    int q = m0 + r;
    if (q < NPU) {
        float sc = s_sc[r];
        float* ht = out + (size_t)B_ * NE_ * D_;
        size_t o1 = ((size_t)(b * P_ + s_p1[r])) * D_ + n0 + half;
        size_t o2 = ((size_t)(b * P_ + s_p2[r])) * D_ + n0 + half;
        const float* crow = &C[r * CSTRIDE + half];
#pragma unroll
        for (int c = 0; c < 64; c += 4) {
            float4 v = make_float4(crow[c] * sc, crow[c + 1] * sc,
                                   crow[c + 2] * sc, crow[c + 3] * sc);
            *(float4*)&ht[o1 + c] = v;
            *(float4*)&ht[o2 + c] = v;
        }
    }
}

// ===========================================================================
extern "C" void kernel_launch(void* const* d_in, const int* in_sizes, int n_in,
                              void* d_out, int out_size) {
    const float* so   = nullptr;
    const float* att  = nullptr;
    const float* mask = nullptr;
    const int*   posw = nullptr;
    const int*   htsw = nullptr;

    for (int k = 0; k < n_in; k++) {
        int sz = in_sizes[k];
        if      (sz == SZ_SO)  so   = (const float*)d_in[k];
        else if (sz == SZ_ATT) att  = (const float*)d_in[k];
        else if (sz == SZ_HTS) htsw = (const int*)d_in[k];
        else if (sz == SZ_MSK) {
            if (!mask) mask = (const float*)d_in[k];
            else       posw = (const int*)d_in[k];
        }
    }
    float* out = (float*)d_out;

    cudaFuncSetAttribute(k_gemm_mma,
                         cudaFuncAttributeMaxDynamicSharedMemorySize, SM_TOT);

    k_prep<<<1, 1024>>>(posw, htsw);
    k_entity_embed<<<B_ * NE_, D_>>>(so, mask, out);
    {
        dim3 g(L_ / 32, D_ / 32, B_);
        dim3 t(32, 8);
        k_transpose<<<g, t>>>(so);
    }
    k_entity_att<<<B_ * NE_ * H_, 256>>>(att, mask);
    {
        dim3 g(NLC, B_);
        k_gram<<<g, 256>>>();
    }
    k_finalize<<<(B_ * NPU + 255) / 256, 256>>>();

    dim3 grid(D_ / 128, MP / 128, B_);
    k_gemm_mma<<<grid, 256, SM_TOT>>>(out);
}

// round 16
// speedup vs baseline: 2.3438x; 1.0985x over previous
#include <cuda_runtime.h>
#include <cuda_fp16.h>
#include <cstdint>
#include <math.h>

// Problem constants
#define B_  4
#define L_  1024
#define D_  768
#define H_  12
#define NE_ 42
#define M_  8
#define P_  (NE_*(NE_-1))      // 1722 ordered pairs
#define NPU 861                // unordered pairs (i<j)
#define MP  896                // NPU padded to 128
#define EPS_H 1.2e-4f
#define EH  (NE_*H_)           // 504
#define LC  16                 // l-chunk for gram
#define NLC (L_/LC)            // 64 chunks

// Input element counts
#define SZ_SO   (B_*L_*D_)
#define SZ_ATT  (B_*H_*L_*L_)
#define SZ_HTS  (B_*P_*2)
#define SZ_MSK  (B_*NE_*M_)

// Scratch (zero-init; pad rows >= NPU stay zero)
__device__ float   g_ea[B_*H_*NE_*L_];     // E [b, h, e, l]
__device__ __half  g_X[B_*MP*L_];          // pair att fp16 [b,q,l]
__device__ __half  g_B[B_*D_*L_];          // SO^T fp16 [b,d,l]
__device__ float   g_xpart[B_*NLC*NPU];
__device__ int     g_p2p[B_*NE_*NE_];
__device__ int     g_pos[B_*NE_*M_];
__device__ int     g_ht [B_*P_*2];

// ===========================================================================
// PTX helpers (baseline ISA only — sm_103 non-'a' target: no tcgen05)
// ===========================================================================
__device__ __forceinline__ uint32_t smem_u32(const void* p) {
    uint32_t a;
    asm("{ .reg .u64 t; cvta.to.shared.u64 t, %1; cvt.u32.u64 %0, t; }"
        : "=r"(a) : "l"(p));
    return a;
}
__device__ __forceinline__ void ldm_x4(uint32_t* r, uint32_t addr) {
    asm volatile("ldmatrix.sync.aligned.m8n8.x4.shared.b16 {%0,%1,%2,%3}, [%4];"
        : "=r"(r[0]), "=r"(r[1]), "=r"(r[2]), "=r"(r[3]) : "r"(addr));
}
__device__ __forceinline__ void mma_f16(float* d, const uint32_t* a,
                                        const uint32_t* b) {
    asm volatile("mma.sync.aligned.m16n8k16.row.col.f32.f16.f16.f32 "
        "{%0,%1,%2,%3}, {%4,%5,%6,%7}, {%8,%9}, {%0,%1,%2,%3};"
        : "+f"(d[0]), "+f"(d[1]), "+f"(d[2]), "+f"(d[3])
        : "r"(a[0]), "r"(a[1]), "r"(a[2]), "r"(a[3]), "r"(b[0]), "r"(b[1]));
}
__device__ __forceinline__ void cpa16(uint32_t s, const void* g) {
    asm volatile("cp.async.cg.shared.global [%0], [%1], 16;" :: "r"(s), "l"(g));
}
#define CP_COMMIT() asm volatile("cp.async.commit_group;" ::: "memory")
#define CP_WAIT(n)  asm volatile("cp.async.wait_group %0;" :: "n"(n) : "memory")

// ===========================================================================
// K0: int width detect + convert + p2p map (one block)
// ===========================================================================
__global__ void k_prep(const int* __restrict__ posw, const int* __restrict__ htsw) {
    __shared__ int s_pos64, s_hts64;
    if (threadIdx.x == 0) {
        int nz = 0;
        for (int w = 1; w < 33; w += 2) nz |= posw[w];
        s_pos64 = (nz == 0) ? 1 : 0;
        nz = 0;
        for (int w = 1; w < 33; w += 2) nz |= htsw[w];
        s_hts64 = (nz == 0) ? 1 : 0;
    }
    __syncthreads();
    int sp = s_pos64 ? 2 : 1;
    for (int t = threadIdx.x; t < B_*NE_*M_; t += blockDim.x)
        g_pos[t] = posw[(size_t)t * sp] + 1;          // fold +OFFSET
    int sh = s_hts64 ? 2 : 1;
    for (int t = threadIdx.x; t < B_*P_*2; t += blockDim.x)
        g_ht[t] = htsw[(size_t)t * sh];
    __syncthreads();
    for (int t = threadIdx.x; t < B_*P_; t += blockDim.x) {
        int b = t / P_;
        int i = g_ht[(size_t)t * 2 + 0];
        int j = g_ht[(size_t)t * 2 + 1];
        g_p2p[(b * NE_ + i) * NE_ + j] = t - b * P_;
    }
}

// ===========================================================================
// K1: entity_embed  (grid = B*NE, block = D)
// ===========================================================================
__global__ void k_entity_embed(const float* __restrict__ so,
                               const float* __restrict__ mask,
                               float* __restrict__ out_ee) {
    int be = blockIdx.x;
    int b = be / NE_;
    int d = threadIdx.x;

    __shared__ int   s_row[M_];
    __shared__ float s_mk[M_];
    if (threadIdx.x < M_) {
        s_mk[threadIdx.x]  = mask[(size_t)be * M_ + threadIdx.x];
        s_row[threadIdx.x] = g_pos[be * M_ + threadIdx.x];
    }
    __syncthreads();

    float v[M_];
    float mx = -INFINITY;
#pragma unroll
    for (int m = 0; m < M_; m++) {
        if (s_mk[m] > 0.f) {
            v[m] = so[((size_t)b * L_ + s_row[m]) * D_ + d];
            mx = fmaxf(mx, v[m]);
        } else v[m] = -INFINITY;
    }
    float s = 0.f;
#pragma unroll
    for (int m = 0; m < M_; m++) s += __expf(v[m] - mx);
    out_ee[(size_t)be * D_ + d] = logf(s) + mx;
}

// ===========================================================================
// K2: entity_att — proven form.  grid = B*NE*H (2016), block = 256.
// ===========================================================================
__global__ __launch_bounds__(256)
void k_entity_att(const float* __restrict__ att,
                  const float* __restrict__ mask) {
    int id = blockIdx.x;
    int h  = id % H_;
    int be = id / H_;
    int b  = be / NE_;
    int e  = be % NE_;

    __shared__ int   s_row[M_];
    __shared__ float s_mk[M_];
    if (threadIdx.x < M_) {
        s_mk[threadIdx.x]  = mask[(size_t)be * M_ + threadIdx.x];
        s_row[threadIdx.x] = g_pos[be * M_ + threadIdx.x];
    }
    __syncthreads();

    float cnt = 0.f;
#pragma unroll
    for (int m = 0; m < M_; m++) cnt += s_mk[m];
    float inv = 1.f / cnt;

    const float4* a4 = (const float4*)(att + ((size_t)(b * H_ + h)) * L_ * L_);
    float4* e4 = (float4*)(g_ea + ((size_t)((b * H_ + h) * NE_ + e)) * L_);

    int t = threadIdx.x;
    float4 acc = make_float4(0.f, 0.f, 0.f, 0.f);
#pragma unroll
    for (int m = 0; m < M_; m++) {
        if (s_mk[m] > 0.f) {
            float4 v = a4[(size_t)s_row[m] * 256 + t];
            acc.x += v.x; acc.y += v.y; acc.z += v.z; acc.w += v.w;
        }
    }
    acc.x *= inv; acc.y *= inv; acc.z *= inv; acc.w *= inv;
    e4[t] = acc;
}

// ===========================================================================
// K2b: transpose + fp16 SO -> g_B [b, d, l]
// ===========================================================================
__global__ void k_transpose(const float* __restrict__ so) {
    __shared__ float t[32][33];
    int b  = blockIdx.z;
    int l0 = blockIdx.x * 32;
    int d0 = blockIdx.y * 32;
    int tx = threadIdx.x, ty = threadIdx.y;

#pragma unroll
    for (int i = 0; i < 4; i++) {
        int l = l0 + ty + i * 8;
        t[ty + i * 8][tx] = so[((size_t)b * L_ + l) * D_ + d0 + tx];
    }
    __syncthreads();
#pragma unroll
    for (int i = 0; i < 4; i++) {
        int d = d0 + ty + i * 8;
        g_B[((size_t)(b * D_ + d)) * L_ + l0 + tx] = __float2half(t[tx][ty + i * 8]);
    }
}

// ===========================================================================
// K3: Gram pair attention (proven shape).  grid = (64, B), block = 256.
// ===========================================================================
__global__ __launch_bounds__(256)
void k_gram() {
    __shared__ float El[LC * 512];            // 32 KB
    int lc = blockIdx.x, b = blockIdx.y;
    int l0 = lc * LC;

    for (int o = threadIdx.x; o < EH * (LC / 4); o += 256) {
        int c = o / (LC / 4), part = o % (LC / 4);
        int e = c / H_, h = c % H_;
        const float4 v = *(const float4*)(g_ea
            + ((size_t)((b * H_ + h) * NE_ + e)) * L_ + l0 + part * 4);
        El[(part * 4 + 0) * 512 + c] = v.x;
        El[(part * 4 + 1) * 512 + c] = v.y;
        El[(part * 4 + 2) * 512 + c] = v.z;
        El[(part * 4 + 3) * 512 + c] = v.w;
    }
    __syncthreads();

    for (int p = threadIdx.x; p < NPU; p += 256) {
        int i = 0, rem = p;
        while (rem >= NE_ - 1 - i) { rem -= NE_ - 1 - i; i++; }
        int j = i + 1 + rem;

        alignas(16) __half hb[LC];
        float lsum = 0.f;
#pragma unroll
        for (int l = 0; l < LC; l++) {
            const float4* a4 = (const float4*)&El[l * 512 + i * H_];
            const float4* c4 = (const float4*)&El[l * 512 + j * H_];
            float4 a0 = a4[0], a1 = a4[1], a2 = a4[2];
            float4 c0 = c4[0], c1 = c4[1], c2 = c4[2];
            float x = a0.x*c0.x + a0.y*c0.y + a0.z*c0.z + a0.w*c0.w
                    + a1.x*c1.x + a1.y*c1.y + a1.z*c1.z + a1.w*c1.w
                    + a2.x*c2.x + a2.y*c2.y + a2.z*c2.z + a2.w*c2.w;
            hb[l] = __float2half(x);
            lsum += x;
        }
        size_t rowb = ((size_t)(b * MP + p)) * L_ + l0;
        const uint4* h4 = (const uint4*)hb;
        *(uint4*)&g_X[rowb]     = h4[0];
        *(uint4*)&g_X[rowb + 8] = h4[1];
        g_xpart[(b * NLC + lc) * NPU + p] = lsum;
    }
}

// ===========================================================================
// K4: single-pass fp16 mma.sync GEMM, 3-stage cp.async pipeline.
//     CTA tile 128(M) x 192(N), BK=32, 256 thr (8 warps = 2m x 4n, 64x48).
//     grid = (D/192=4, MP/128=7, B) = 112 CTAs -> ONE wave, 1 CTA/SM.
// SMEM stage (25600 B): A[128 rows][80B] @0, B[192 rows][80B] @10240.
// 3 stages = 76800.  Epilogue reuses smem as C[128][196] f32 (100352).
// Scale finalize (sum of 64 l-chunk partials) folded into epilogue.
// ===========================================================================
#define TS2     80
#define STG     25600
#define SBO     10240
#define CSTRIDE 196
#define SM_TOT  (128*CSTRIDE*4)    // 100352

__global__ __launch_bounds__(256, 1)
void k_gemm_mma(float* __restrict__ out) {
    extern __shared__ char smem[];
    uint32_t sb = smem_u32(smem);

    int tid = threadIdx.x;
    int wid = tid >> 5, lane = tid & 31;
    int gid = lane >> 2, tig = lane & 3;
    int wm = wid >> 2, wn = wid & 3;         // 2(m) x 4(n)
    int b  = blockIdx.z;
    int m0 = blockIdx.y * 128;
    int n0 = blockIdx.x * 192;

    const uint4* Ag = (const uint4*)g_X;     // row = 128 uint4 (1024 fp16)
    const uint4* Bg = (const uint4*)g_B;
    int arow0 = (b * MP + m0) * 128;
    int brow0 = (b * D_ + n0) * 128;

    // ldmatrix lane addressing
    int sub = lane >> 3, lrow = lane & 7;
    int a_r = wm * 64 + lrow + (sub & 1) * 8;
    int a_k = (sub >> 1) * 8;
    int b_r = wn * 48 + lrow + (sub >> 1) * 8;
    int b_k = (sub & 1) * 8;

    float acc[4][6][4];
#pragma unroll
    for (int mt = 0; mt < 4; mt++)
#pragma unroll
        for (int nt = 0; nt < 6; nt++)
#pragma unroll
            for (int r = 0; r < 4; r++) acc[mt][nt][r] = 0.f;

#define LOAD_STAGE(it, slot) do {                                           \
    uint32_t s0 = sb + (slot) * STG;                                        \
    _Pragma("unroll")                                                       \
    for (int c = 0; c < 2; c++) {                                           \
        int idx = tid + c * 256;                                            \
        int row = idx >> 2, seg = idx & 3;                                  \
        cpa16(s0 + row * TS2 + seg * 16,                                    \
              Ag + arow0 + row * 128 + (it) * 4 + seg);                     \
    }                                                                       \
    _Pragma("unroll")                                                       \
    for (int c = 0; c < 3; c++) {                                           \
        int idx = tid + c * 256;                                            \
        int row = idx >> 2, seg = idx & 3;                                  \
        cpa16(s0 + SBO + row * TS2 + seg * 16,                              \
              Bg + brow0 + row * 128 + (it) * 4 + seg);                     \
    }                                                                       \
} while (0)

    LOAD_STAGE(0, 0); CP_COMMIT();
    LOAD_STAGE(1, 1); CP_COMMIT();

    for (int it = 0; it < 32; it++) {
        CP_WAIT(1);
        __syncthreads();
        if (it + 2 < 32) {
            LOAD_STAGE(it + 2, (it + 2) % 3);
            CP_COMMIT();
        }

        uint32_t s0 = sb + (it % 3) * STG;
#pragma unroll
        for (int ks = 0; ks < 2; ks++) {
            uint32_t a[4][4], bb[6][2];
            int kofs = (ks * 16 + a_k) * 2;
#pragma unroll
            for (int mt = 0; mt < 4; mt++)
                ldm_x4(a[mt], s0 + (a_r + mt * 16) * TS2 + kofs);
            int kofsb = (ks * 16 + b_k) * 2;
#pragma unroll
            for (int np = 0; np < 3; np++) {
                uint32_t t4[4];
                ldm_x4(t4, s0 + SBO + (b_r + np * 16) * TS2 + kofsb);
                bb[np*2][0] = t4[0];   bb[np*2][1] = t4[1];
                bb[np*2+1][0] = t4[2]; bb[np*2+1][1] = t4[3];
            }
#pragma unroll
            for (int mt = 0; mt < 4; mt++)
#pragma unroll
                for (int nt = 0; nt < 6; nt++)
                    mma_f16(acc[mt][nt], a[mt], bb[nt]);
        }
    }
    __syncthreads();   // all operand reads done; reuse smem as C

    // -------- epilogue: acc -> SMEM C, fused scale finalize, dual scatter ---
    __shared__ float s_sc[128];
    __shared__ int   s_p1[128], s_p2[128];

    float* C = (float*)smem;
#pragma unroll
    for (int mt = 0; mt < 4; mt++) {
        int rm = wm * 64 + mt * 16 + gid;
#pragma unroll
        for (int nt = 0; nt < 6; nt++) {
            int cn = wn * 48 + nt * 8 + tig * 2;
            *(float2*)&C[rm * CSTRIDE + cn]       = make_float2(acc[mt][nt][0], acc[mt][nt][1]);
            *(float2*)&C[(rm + 8) * CSTRIDE + cn] = make_float2(acc[mt][nt][2], acc[mt][nt][3]);
        }
    }
    if (tid < 128) {
        int q = m0 + tid;
        if (q < NPU) {
            float s = 0.f;
#pragma unroll
            for (int c = 0; c < NLC; c++)
                s += g_xpart[(b * NLC + c) * NPU + q];
            s_sc[tid] = 1.f / (s + EPS_H);
            int i = 0, rem = q;
            while (rem >= NE_ - 1 - i) { rem -= NE_ - 1 - i; i++; }
            int j = i + 1 + rem;
            s_p1[tid] = g_p2p[(b * NE_ + i) * NE_ + j];
            s_p2[tid] = g_p2p[(b * NE_ + j) * NE_ + i];
        }
    }
    __syncthreads();

    int r    = tid >> 1;
    int half = (tid & 1) * 96;
    int q = m0 + r;
    if (q < NPU) {
        float sc = s_sc[r];
        float* ht = out + (size_t)B_ * NE_ * D_;
        size_t o1 = ((size_t)(b * P_ + s_p1[r])) * D_ + n0 + half;
        size_t o2 = ((size_t)(b * P_ + s_p2[r])) * D_ + n0 + half;
        const float* crow = &C[r * CSTRIDE + half];
#pragma unroll
        for (int c = 0; c < 96; c += 4) {
            float4 v = make_float4(crow[c] * sc, crow[c + 1] * sc,
                                   crow[c + 2] * sc, crow[c + 3] * sc);
            *(float4*)&ht[o1 + c] = v;
            *(float4*)&ht[o2 + c] = v;
        }
    }
}

// ===========================================================================
extern "C" void kernel_launch(void* const* d_in, const int* in_sizes, int n_in,
                              void* d_out, int out_size) {
    const float* so   = nullptr;
    const float* att  = nullptr;
    const float* mask = nullptr;
    const int*   posw = nullptr;
    const int*   htsw = nullptr;

    for (int k = 0; k < n_in; k++) {
        int sz = in_sizes[k];
        if      (sz == SZ_SO)  so   = (const float*)d_in[k];
        else if (sz == SZ_ATT) att  = (const float*)d_in[k];
        else if (sz == SZ_HTS) htsw = (const int*)d_in[k];
        else if (sz == SZ_MSK) {
            if (!mask) mask = (const float*)d_in[k];
            else       posw = (const int*)d_in[k];
        }
    }
    float* out = (float*)d_out;

    cudaFuncSetAttribute(k_gemm_mma,
                         cudaFuncAttributeMaxDynamicSharedMemorySize, SM_TOT);

    k_prep<<<1, 1024>>>(posw, htsw);
    k_entity_embed<<<B_ * NE_, D_>>>(so, mask, out);
    {
        dim3 g(L_ / 32, D_ / 32, B_);
        dim3 t(32, 8);
        k_transpose<<<g, t>>>(so);
    }
    k_entity_att<<<B_ * NE_ * H_, 256>>>(att, mask);
    {
        dim3 g(NLC, B_);
        k_gram<<<g, 256>>>();
    }

    dim3 grid(D_ / 192, MP / 128, B_);
    k_gemm_mma<<<grid, 256, SM_TOT>>>(out);
}